// round 12
// baseline (speedup 1.0000x reference)
#include <cuda_runtime.h>
#include <cuda_fp16.h>
#include <cstdint>

// ============================================================================
// Problem dims
// ============================================================================
static constexpr int Mtot = 8192;
static constexpr int Hdim = 4096;
static constexpr int Idim = 11008;

static constexpr int BM = 128;
static constexpr int MT = Mtot / BM;          // 64
static constexpr int BK = 64;                 // halves per k-chunk (128B rows)
static constexpr int NST = 4;

// gate/up: CTA 128M x 128N per output (2 outputs). 8 warps 2m x 4n; warp 64x32/output.
static constexpr int NT_GU  = Idim / 128;     // 86
static constexpr int NCH_GU = Hdim / BK;      // 64
static constexpr int STG_GU = 49152;          // A 16K, Bg 16K, Bu 16K
static constexpr int SMEM_GU = NST * STG_GU;  // 196608

// down: CTA 128M x 256N. 8 warps 2m x 4n; warp 64x64.
static constexpr int NT_DN  = Hdim / 256;     // 16
static constexpr int NCH_DN = Idim / BK;      // 172
static constexpr int STG_DN = 49152;          // A 16K, B 32K
static constexpr int SMEM_DN = NST * STG_DN;  // 196608

// ============================================================================
// Device scratch
// ============================================================================
__device__ __half g_gw16[(size_t)Idim * Hdim];
__device__ __half g_uw16[(size_t)Idim * Hdim];
__device__ __half g_dw16[(size_t)Hdim * Idim];
__device__ __half g_x16 [(size_t)Mtot * Hdim];
__device__ __half g_p16 [(size_t)Mtot * Idim];

// ============================================================================
// Primitives (sm_80-era PTX; compute_103-safe)
// ============================================================================
__device__ __forceinline__ uint32_t smem_u32(const void* p) {
    uint32_t a;
    asm("{ .reg .u64 t; cvta.to.shared.u64 t, %1; cvt.u32.u64 %0, t; }" : "=r"(a) : "l"(p));
    return a;
}
__device__ __forceinline__ void cpa16(uint32_t s, const void* g) {
    asm volatile("cp.async.cg.shared.global [%0], [%1], 16;" :: "r"(s), "l"(g));
}
#define CP_COMMIT() asm volatile("cp.async.commit_group;" ::: "memory")
#define CP_WAIT(N)  asm volatile("cp.async.wait_group %0;" :: "n"(N) : "memory")

#define LDSM4(r, addr) \
    asm volatile("ldmatrix.sync.aligned.m8n8.x4.shared.b16 {%0,%1,%2,%3}, [%4];" \
        : "=r"((r)[0]), "=r"((r)[1]), "=r"((r)[2]), "=r"((r)[3]) : "r"(addr))

#define MMAF16(d, a, b0, b1) \
    asm volatile("mma.sync.aligned.m16n8k16.row.col.f32.f16.f16.f32 " \
        "{%0,%1,%2,%3}, {%4,%5,%6,%7}, {%8,%9}, {%0,%1,%2,%3};" \
        : "+f"((d)[0]), "+f"((d)[1]), "+f"((d)[2]), "+f"((d)[3]) \
        : "r"((a)[0]), "r"((a)[1]), "r"((a)[2]), "r"((a)[3]), "r"(b0), "r"(b1))

// 128B rows, 8x16B chunks, swizzle c ^= (r&7): conflict-free (validated R7-R11).
__device__ __forceinline__ uint32_t swz(uint32_t base, int r, int c) {
    return base + r * 128 + (((c ^ (r & 7)) & 7) << 4);
}
__device__ __forceinline__ uint32_t swzoff(int r, int c) {
    return (uint32_t)(r * 128 + (((c ^ (r & 7)) & 7) << 4));
}

__device__ __forceinline__ void tile_coords(int bid, int nt, int& mt, int& ntile) {
    const int GROUP_M = 8;
    int per_group = GROUP_M * nt;
    int g = bid / per_group;
    int r = bid % per_group;
    int base = g * GROUP_M;
    int gm = MT - base; if (gm > GROUP_M) gm = GROUP_M;
    mt = base + (r % gm);
    ntile = r / gm;
}

// ============================================================================
// Prep: weights -> fp16 (exact, |w|<=127); x -> fp16 (RN)
// ============================================================================
__global__ void pack_weights(const int* __restrict__ gq, const int* __restrict__ uq,
                             const int* __restrict__ dq) {
    size_t i = (size_t)blockIdx.x * blockDim.x + threadIdx.x;
    size_t n4 = (size_t)Idim * Hdim / 4;
    if (i >= n4) return;
    int4 a = reinterpret_cast<const int4*>(gq)[i];
    int4 b = reinterpret_cast<const int4*>(uq)[i];
    int4 c = reinterpret_cast<const int4*>(dq)[i];
    __half2 a0 = __floats2half2_rn((float)a.x, (float)a.y);
    __half2 a1 = __floats2half2_rn((float)a.z, (float)a.w);
    __half2 b0 = __floats2half2_rn((float)b.x, (float)b.y);
    __half2 b1 = __floats2half2_rn((float)b.z, (float)b.w);
    __half2 c0 = __floats2half2_rn((float)c.x, (float)c.y);
    __half2 c1 = __floats2half2_rn((float)c.z, (float)c.w);
    reinterpret_cast<uint2*>(g_gw16)[i] =
        make_uint2(*reinterpret_cast<uint32_t*>(&a0), *reinterpret_cast<uint32_t*>(&a1));
    reinterpret_cast<uint2*>(g_uw16)[i] =
        make_uint2(*reinterpret_cast<uint32_t*>(&b0), *reinterpret_cast<uint32_t*>(&b1));
    reinterpret_cast<uint2*>(g_dw16)[i] =
        make_uint2(*reinterpret_cast<uint32_t*>(&c0), *reinterpret_cast<uint32_t*>(&c1));
}

__global__ void cvt_x(const float* __restrict__ x) {
    size_t i = (size_t)blockIdx.x * blockDim.x + threadIdx.x;
    size_t n4 = (size_t)Mtot * Hdim / 4;
    if (i >= n4) return;
    float4 v = reinterpret_cast<const float4*>(x)[i];
    __half2 h0 = __floats2half2_rn(v.x, v.y);
    __half2 h1 = __floats2half2_rn(v.z, v.w);
    reinterpret_cast<uint2*>(g_x16)[i] =
        make_uint2(*reinterpret_cast<uint32_t*>(&h0), *reinterpret_cast<uint32_t*>(&h1));
}

// ============================================================================
// Kernel A: fused gate+up fp16 GEMM -> p = (g*gs)*(u*us) in fp16
// CTA: 256 threads, 1 CTA/SM. 8 warps 2m x 4n; warp 64(M) x 32(N) per output.
// NST=4 x 48KB stages; frag double-buffer + partial step-3 deferral.
// ============================================================================
__global__ __launch_bounds__(256, 1)
void gemm_gateup(const float* __restrict__ gate_scale, const float* __restrict__ up_scale) {
    extern __shared__ __align__(128) char smem[];
    const uint32_t s0 = smem_u32(smem);
    const int tid = threadIdx.x;
    const int wid = tid >> 5, lane = tid & 31;
    const int rsel = lane & 15, csel = lane >> 4;
    const int wm = (wid & 1) * 64, wn = (wid >> 1) * 32;   // 2m x 4n

    int mt, nt; tile_coords(blockIdx.x, NT_GU, mt, nt);
    const int m0 = mt * BM, n0 = nt * 128;

    const __half* pA  = g_x16  + (size_t)m0 * Hdim;
    const __half* pBg = g_gw16 + (size_t)n0 * Hdim;
    const __half* pBu = g_uw16 + (size_t)n0 * Hdim;

    // loader: lr = row (0..31), lc = 16B chunk (0..7); 12 cpa/thread/chunk
    const int lr = tid >> 3, lc = tid & 7;

    auto load_chunk = [&](int ch, int st) {   // full-chunk load (prologue only)
        uint32_t sb = s0 + st * STG_GU;
        size_t gk = (size_t)ch * BK + lc * 8;
        #pragma unroll
        for (int j = 0; j < 4; ++j) {
            cpa16(sb + swzoff(lr + 32 * j, lc),         pA  + (size_t)(lr + 32 * j) * Hdim + gk);
            cpa16(sb + 16384 + swzoff(lr + 32 * j, lc), pBg + (size_t)(lr + 32 * j) * Hdim + gk);
            cpa16(sb + 32768 + swzoff(lr + 32 * j, lc), pBu + (size_t)(lr + 32 * j) * Hdim + gk);
        }
        CP_COMMIT();
    };

    float cg[4][4][4], cu[4][4][4];
    #pragma unroll
    for (int g = 0; g < 4; ++g)
        #pragma unroll
        for (int n = 0; n < 4; ++n)
            #pragma unroll
            for (int j = 0; j < 4; ++j) { cg[g][n][j] = 0.f; cu[g][n][j] = 0.f; }

    load_chunk(0, 0);
    load_chunk(1, 1);
    load_chunk(2, 2);

    uint32_t ah[2][4][4], bg[2][2][4], bu[2][2][4];   // buffer 1 partially live across

    for (int ch = 0; ch < NCH_GU; ++ch) {
        CP_WAIT(2);
        __syncthreads();
        const int nx = ch + 3;
        const bool pf = nx < NCH_GU;
        const uint32_t sb = s0 + (ch % NST) * STG_GU;
        const uint32_t nb = s0 + (nx % NST) * STG_GU;
        const size_t gk = (size_t)nx * BK + lc * 8;

        // step-0 fragments into buffer 0
        {
            const int cc = csel;
            #pragma unroll
            for (int g = 0; g < 4; ++g)
                LDSM4(ah[0][g], swz(sb, wm + g * 16 + rsel, cc));
            #pragma unroll
            for (int bt = 0; bt < 2; ++bt) {
                LDSM4(bg[0][bt], swz(sb + 16384, wn + bt * 16 + rsel, cc));
                LDSM4(bu[0][bt], swz(sb + 32768, wn + bt * 16 + rsel, cc));
            }
        }
        // deferred MMAs: previous chunk's step-3, n=0..1 (ah[1], bg[1][0], bu[1][0])
        if (ch) {
            #pragma unroll
            for (int g = 0; g < 4; ++g)
                #pragma unroll
                for (int n = 0; n < 2; ++n) {
                    MMAF16(cg[g][n], ah[1][g], bg[1][0][n], bg[1][0][2 + n]);
                    MMAF16(cu[g][n], ah[1][g], bu[1][0][n], bu[1][0][2 + n]);
                }
        }
        #pragma unroll
        for (int s = 0; s < 4; ++s) {
            const int cur = s & 1;
            if (s < 3) {                       // load next step's frags
                const int cc = 2 * (s + 1) + csel;
                #pragma unroll
                for (int g = 0; g < 4; ++g)
                    LDSM4(ah[cur ^ 1][g], swz(sb, wm + g * 16 + rsel, cc));
                #pragma unroll
                for (int bt = 0; bt < 2; ++bt) {
                    LDSM4(bg[cur ^ 1][bt], swz(sb + 16384, wn + bt * 16 + rsel, cc));
                    LDSM4(bu[cur ^ 1][bt], swz(sb + 32768, wn + bt * 16 + rsel, cc));
                }
            }
            if (pf) {                          // 3 of 12 next-chunk prefetches
                cpa16(nb + swzoff(lr + 32 * s, lc),
                      pA + (size_t)(lr + 32 * s) * Hdim + gk);
                cpa16(nb + 16384 + swzoff(lr + 32 * s, lc),
                      pBg + (size_t)(lr + 32 * s) * Hdim + gk);
                cpa16(nb + 32768 + swzoff(lr + 32 * s, lc),
                      pBu + (size_t)(lr + 32 * s) * Hdim + gk);
            }
            if (s < 3) {                       // full MMA set for steps 0..2
                #pragma unroll
                for (int g = 0; g < 4; ++g)
                    #pragma unroll
                    for (int n = 0; n < 4; ++n) {
                        int bt = n >> 1, sub = n & 1;
                        MMAF16(cg[g][n], ah[cur][g], bg[cur][bt][sub], bg[cur][bt][2 + sub]);
                        MMAF16(cu[g][n], ah[cur][g], bu[cur][bt][sub], bu[cur][bt][2 + sub]);
                    }
            } else {                           // step 3: issue n=2..3 now; n=0..1 deferred
                #pragma unroll
                for (int g = 0; g < 4; ++g)
                    #pragma unroll
                    for (int n = 2; n < 4; ++n) {
                        int sub = n & 1;
                        MMAF16(cg[g][n], ah[1][g], bg[1][1][sub], bg[1][1][2 + sub]);
                        MMAF16(cu[g][n], ah[1][g], bu[1][1][sub], bu[1][1][2 + sub]);
                    }
            }
        }
        if (pf) CP_COMMIT();
    }
    // drain final chunk's deferred n=0..1
    #pragma unroll
    for (int g = 0; g < 4; ++g)
        #pragma unroll
        for (int n = 0; n < 2; ++n) {
            MMAF16(cg[g][n], ah[1][g], bg[1][0][n], bg[1][0][2 + n]);
            MMAF16(cu[g][n], ah[1][g], bu[1][0][n], bu[1][0][2 + n]);
        }

    // Epilogue: p = (g*gs)*(u*us) -> half2
    #pragma unroll
    for (int n = 0; n < 4; ++n) {
        const int cn = n0 + wn + n * 8 + (lane & 3) * 2;
        const float gs0 = gate_scale[cn], gs1 = gate_scale[cn + 1];
        const float us0 = up_scale[cn],   us1 = up_scale[cn + 1];
        #pragma unroll
        for (int g = 0; g < 4; ++g) {
            const int rr = m0 + wm + g * 16 + (lane >> 2);
            float p00 = (cg[g][n][0] * gs0) * (cu[g][n][0] * us0);
            float p01 = (cg[g][n][1] * gs1) * (cu[g][n][1] * us1);
            float p10 = (cg[g][n][2] * gs0) * (cu[g][n][2] * us0);
            float p11 = (cg[g][n][3] * gs1) * (cu[g][n][3] * us1);
            __half2 q0 = __floats2half2_rn(p00, p01);
            __half2 q1 = __floats2half2_rn(p10, p11);
            *reinterpret_cast<__half2*>(&g_p16[(size_t)rr * Idim + cn]) = q0;
            *reinterpret_cast<__half2*>(&g_p16[(size_t)(rr + 8) * Idim + cn]) = q1;
        }
    }
}

// ============================================================================
// Kernel B: down GEMM.  out = down_scale * (p @ dw^T)
// CTA: 256 threads, 1 CTA/SM. 8 warps 2m x 4n; warp 64(M) x 64(N). CTA 128x256.
// NST=4 x 48KB stages; frag double-buffer + partial step-3 deferral.
// ============================================================================
__global__ __launch_bounds__(256, 1)
void gemm_down(const float* __restrict__ down_scale, float* __restrict__ out) {
    extern __shared__ __align__(128) char smem[];
    const uint32_t s0 = smem_u32(smem);
    const int tid = threadIdx.x;
    const int wid = tid >> 5, lane = tid & 31;
    const int rsel = lane & 15, csel = lane >> 4;
    const int wm = (wid & 1) * 64, wn = (wid >> 1) * 64;   // 2m x 4n

    int mt, nt; tile_coords(blockIdx.x, NT_DN, mt, nt);
    const int m0 = mt * BM, n0 = nt * 256;

    const __half* pA = g_p16  + (size_t)m0 * Idim;
    const __half* pB = g_dw16 + (size_t)n0 * Idim;

    const int lr = tid >> 3, lc = tid & 7;

    auto load_chunk = [&](int ch, int st) {   // full-chunk load (prologue only)
        uint32_t sb = s0 + st * STG_DN;
        size_t gk = (size_t)ch * BK + lc * 8;
        #pragma unroll
        for (int j = 0; j < 4; ++j)
            cpa16(sb + swzoff(lr + 32 * j, lc), pA + (size_t)(lr + 32 * j) * Idim + gk);
        #pragma unroll
        for (int j = 0; j < 8; ++j)
            cpa16(sb + 16384 + swzoff(lr + 32 * j, lc), pB + (size_t)(lr + 32 * j) * Idim + gk);
        CP_COMMIT();
    };

    float cd[4][8][4];
    #pragma unroll
    for (int g = 0; g < 4; ++g)
        #pragma unroll
        for (int n = 0; n < 8; ++n)
            #pragma unroll
            for (int j = 0; j < 4; ++j) cd[g][n][j] = 0.f;

    load_chunk(0, 0);
    load_chunk(1, 1);
    load_chunk(2, 2);

    uint32_t ah[2][4][4], bb[2][4][4];        // buffer 1 partially live across

    for (int ch = 0; ch < NCH_DN; ++ch) {
        CP_WAIT(2);
        __syncthreads();
        const int nx = ch + 3;
        const bool pf = nx < NCH_DN;
        const uint32_t sb = s0 + (ch % NST) * STG_DN;
        const uint32_t nb = s0 + (nx % NST) * STG_DN;
        const size_t gk = (size_t)nx * BK + lc * 8;

        // step-0 fragments into buffer 0
        {
            const int cc = csel;
            #pragma unroll
            for (int g = 0; g < 4; ++g)
                LDSM4(ah[0][g], swz(sb, wm + g * 16 + rsel, cc));
            #pragma unroll
            for (int bt = 0; bt < 4; ++bt)
                LDSM4(bb[0][bt], swz(sb + 16384, wn + bt * 16 + rsel, cc));
        }
        // deferred MMAs: previous chunk's step-3, n=0..3 (ah[1], bb[1][0..1])
        if (ch) {
            #pragma unroll
            for (int g = 0; g < 4; ++g)
                #pragma unroll
                for (int n = 0; n < 4; ++n) {
                    int bt = n >> 1, sub = n & 1;
                    MMAF16(cd[g][n], ah[1][g], bb[1][bt][sub], bb[1][bt][2 + sub]);
                }
        }
        #pragma unroll
        for (int s = 0; s < 4; ++s) {
            const int cur = s & 1;
            if (s < 3) {
                const int cc = 2 * (s + 1) + csel;
                #pragma unroll
                for (int g = 0; g < 4; ++g)
                    LDSM4(ah[cur ^ 1][g], swz(sb, wm + g * 16 + rsel, cc));
                #pragma unroll
                for (int bt = 0; bt < 4; ++bt)
                    LDSM4(bb[cur ^ 1][bt], swz(sb + 16384, wn + bt * 16 + rsel, cc));
            }
            if (pf) {                          // 3 of 12 next-chunk prefetches
                cpa16(nb + swzoff(lr + 32 * s, lc),
                      pA + (size_t)(lr + 32 * s) * Idim + gk);
                cpa16(nb + 16384 + swzoff(lr + 32 * (2 * s), lc),
                      pB + (size_t)(lr + 32 * (2 * s)) * Idim + gk);
                cpa16(nb + 16384 + swzoff(lr + 32 * (2 * s + 1), lc),
                      pB + (size_t)(lr + 32 * (2 * s + 1)) * Idim + gk);
            }
            if (s < 3) {                       // full MMA set for steps 0..2
                #pragma unroll
                for (int g = 0; g < 4; ++g)
                    #pragma unroll
                    for (int n = 0; n < 8; ++n) {
                        int bt = n >> 1, sub = n & 1;
                        MMAF16(cd[g][n], ah[cur][g], bb[cur][bt][sub], bb[cur][bt][2 + sub]);
                    }
            } else {                           // step 3: issue n=4..7 now; n=0..3 deferred
                #pragma unroll
                for (int g = 0; g < 4; ++g)
                    #pragma unroll
                    for (int n = 4; n < 8; ++n) {
                        int bt = n >> 1, sub = n & 1;
                        MMAF16(cd[g][n], ah[1][g], bb[1][bt][sub], bb[1][bt][2 + sub]);
                    }
            }
        }
        if (pf) CP_COMMIT();
    }
    // drain final chunk's deferred n=0..3
    #pragma unroll
    for (int g = 0; g < 4; ++g)
        #pragma unroll
        for (int n = 0; n < 4; ++n) {
            int bt = n >> 1, sub = n & 1;
            MMAF16(cd[g][n], ah[1][g], bb[1][bt][sub], bb[1][bt][2 + sub]);
        }

    #pragma unroll
    for (int n = 0; n < 8; ++n) {
        const int cn = n0 + wn + n * 8 + (lane & 3) * 2;
        const float ds0 = down_scale[cn], ds1 = down_scale[cn + 1];
        #pragma unroll
        for (int g = 0; g < 4; ++g) {
            const int rr = m0 + wm + g * 16 + (lane >> 2);
            float2 v0 = make_float2(cd[g][n][0] * ds0, cd[g][n][1] * ds1);
            float2 v1 = make_float2(cd[g][n][2] * ds0, cd[g][n][3] * ds1);
            *reinterpret_cast<float2*>(&out[(size_t)rr * Hdim + cn]) = v0;
            *reinterpret_cast<float2*>(&out[(size_t)(rr + 8) * Hdim + cn]) = v1;
        }
    }
}

// ============================================================================
// Launch
// ============================================================================
extern "C" void kernel_launch(void* const* d_in, const int* in_sizes, int n_in,
                              void* d_out, int out_size) {
    (void)in_sizes; (void)n_in; (void)out_size;
    const float* x          = (const float*)d_in[0];
    const int*   gate_wq    = (const int*)  d_in[1];
    const float* gate_scale = (const float*)d_in[2];
    const int*   up_wq      = (const int*)  d_in[3];
    const float* up_scale   = (const float*)d_in[4];
    const int*   down_wq    = (const int*)  d_in[5];
    const float* down_scale = (const float*)d_in[6];
    float* out = (float*)d_out;

    cudaFuncSetAttribute(gemm_gateup, cudaFuncAttributeMaxDynamicSharedMemorySize, SMEM_GU);
    cudaFuncSetAttribute(gemm_down,   cudaFuncAttributeMaxDynamicSharedMemorySize, SMEM_DN);

    size_t n4 = (size_t)Idim * Hdim / 4;
    pack_weights<<<(unsigned)((n4 + 255) / 256), 256>>>(gate_wq, up_wq, down_wq);
    size_t nx4 = (size_t)Mtot * Hdim / 4;
    cvt_x<<<(unsigned)((nx4 + 255) / 256), 256>>>(x);

    gemm_gateup<<<MT * NT_GU, 256, SMEM_GU>>>(gate_scale, up_scale);
    gemm_down<<<MT * NT_DN, 256, SMEM_DN>>>(down_scale, out);
}

// round 14
// speedup vs baseline: 1.6678x; 1.6678x over previous
#include <cuda_runtime.h>
#include <cuda_fp16.h>
#include <cstdint>

// ============================================================================
// Problem dims
// ============================================================================
static constexpr int Mtot = 8192;
static constexpr int Hdim = 4096;
static constexpr int Idim = 11008;

static constexpr int BM = 128;
static constexpr int MT = Mtot / BM;          // 64
static constexpr int BK = 64;                 // halves per k-chunk (128B rows)
static constexpr int NST = 3;

// gate/up: CTA 128M x 64N(per output), 4 warps (2m x 2n), warp 64x32 per output
static constexpr int NT_GU  = Idim / 64;      // 172
static constexpr int NCH_GU = Hdim / BK;      // 64
static constexpr int STG_GU = 32768;          // A 16K, Bg 8K, Bu 8K
static constexpr int SMEM_GU = NST * STG_GU;  // 98304

// down: CTA 128M x 128N, 4 warps (2m x 2n), warp 64x64
static constexpr int NT_DN  = Hdim / 128;     // 32
static constexpr int NCH_DN = Idim / BK;      // 172
static constexpr int STG_DN = 32768;          // A 16K, B 16K
static constexpr int SMEM_DN = NST * STG_DN;  // 98304

// ============================================================================
// Device scratch
// ============================================================================
__device__ __half g_gw16[(size_t)Idim * Hdim];
__device__ __half g_uw16[(size_t)Idim * Hdim];
__device__ __half g_dw16[(size_t)Hdim * Idim];
__device__ __half g_x16 [(size_t)Mtot * Hdim];
__device__ __half g_p16 [(size_t)Mtot * Idim];

// ============================================================================
// Primitives (sm_80-era PTX; compute_103-safe)
// ============================================================================
__device__ __forceinline__ uint32_t smem_u32(const void* p) {
    uint32_t a;
    asm("{ .reg .u64 t; cvta.to.shared.u64 t, %1; cvt.u32.u64 %0, t; }" : "=r"(a) : "l"(p));
    return a;
}
__device__ __forceinline__ void cpa16(uint32_t s, const void* g) {
    asm volatile("cp.async.cg.shared.global [%0], [%1], 16;" :: "r"(s), "l"(g));
}
#define CP_COMMIT() asm volatile("cp.async.commit_group;" ::: "memory")
#define CP_WAIT(N)  asm volatile("cp.async.wait_group %0;" :: "n"(N) : "memory")

#define LDSM4(r, addr) \
    asm volatile("ldmatrix.sync.aligned.m8n8.x4.shared.b16 {%0,%1,%2,%3}, [%4];" \
        : "=r"((r)[0]), "=r"((r)[1]), "=r"((r)[2]), "=r"((r)[3]) : "r"(addr))

#define MMAF16(d, a, b0, b1) \
    asm volatile("mma.sync.aligned.m16n8k16.row.col.f32.f16.f16.f32 " \
        "{%0,%1,%2,%3}, {%4,%5,%6,%7}, {%8,%9}, {%0,%1,%2,%3};" \
        : "+f"((d)[0]), "+f"((d)[1]), "+f"((d)[2]), "+f"((d)[3]) \
        : "r"((a)[0]), "r"((a)[1]), "r"((a)[2]), "r"((a)[3]), "r"(b0), "r"(b1))

// 128B rows, 8x16B chunks, swizzle c ^= (r&7): conflict-free for both
// cp.async stores and ldmatrix reads (validated R7-R12).
__device__ __forceinline__ uint32_t swz(uint32_t base, int r, int c) {
    return base + r * 128 + (((c ^ (r & 7)) & 7) << 4);
}
__device__ __forceinline__ uint32_t swzoff(int r, int c) {
    return (uint32_t)(r * 128 + (((c ^ (r & 7)) & 7) << 4));
}

__device__ __forceinline__ void tile_coords(int bid, int nt, int& mt, int& ntile) {
    const int GROUP_M = 8;
    int per_group = GROUP_M * nt;
    int g = bid / per_group;
    int r = bid % per_group;
    int base = g * GROUP_M;
    int gm = MT - base; if (gm > GROUP_M) gm = GROUP_M;
    mt = base + (r % gm);
    ntile = r / gm;
}

// ============================================================================
// Prep: weights -> fp16 (exact, |w|<=127); x -> fp16 (RN)
// ============================================================================
__global__ void pack_weights(const int* __restrict__ gq, const int* __restrict__ uq,
                             const int* __restrict__ dq) {
    size_t i = (size_t)blockIdx.x * blockDim.x + threadIdx.x;
    size_t n4 = (size_t)Idim * Hdim / 4;
    if (i >= n4) return;
    int4 a = reinterpret_cast<const int4*>(gq)[i];
    int4 b = reinterpret_cast<const int4*>(uq)[i];
    int4 c = reinterpret_cast<const int4*>(dq)[i];
    __half2 a0 = __floats2half2_rn((float)a.x, (float)a.y);
    __half2 a1 = __floats2half2_rn((float)a.z, (float)a.w);
    __half2 b0 = __floats2half2_rn((float)b.x, (float)b.y);
    __half2 b1 = __floats2half2_rn((float)b.z, (float)b.w);
    __half2 c0 = __floats2half2_rn((float)c.x, (float)c.y);
    __half2 c1 = __floats2half2_rn((float)c.z, (float)c.w);
    reinterpret_cast<uint2*>(g_gw16)[i] =
        make_uint2(*reinterpret_cast<uint32_t*>(&a0), *reinterpret_cast<uint32_t*>(&a1));
    reinterpret_cast<uint2*>(g_uw16)[i] =
        make_uint2(*reinterpret_cast<uint32_t*>(&b0), *reinterpret_cast<uint32_t*>(&b1));
    reinterpret_cast<uint2*>(g_dw16)[i] =
        make_uint2(*reinterpret_cast<uint32_t*>(&c0), *reinterpret_cast<uint32_t*>(&c1));
}

__global__ void cvt_x(const float* __restrict__ x) {
    size_t i = (size_t)blockIdx.x * blockDim.x + threadIdx.x;
    size_t n4 = (size_t)Mtot * Hdim / 4;
    if (i >= n4) return;
    float4 v = reinterpret_cast<const float4*>(x)[i];
    __half2 h0 = __floats2half2_rn(v.x, v.y);
    __half2 h1 = __floats2half2_rn(v.z, v.w);
    reinterpret_cast<uint2*>(g_x16)[i] =
        make_uint2(*reinterpret_cast<uint32_t*>(&h0), *reinterpret_cast<uint32_t*>(&h1));
}

// ============================================================================
// Kernel A: fused gate+up fp16 GEMM -> p = (g*gs)*(u*us) in fp16
// CTA: 128 threads, 2/SM. 4 warps 2m x 2n; warp 64(M) x 32(N) per output.
// Frag double-buffer + partial step-3 deferral + PARITY K-ROTATION:
// odd CTAs start the k-loop at NCH/2 (wrapping), desynchronizing the two
// co-resident CTAs' memory bursts and barrier phases.
// ============================================================================
__global__ __launch_bounds__(128, 2)
void gemm_gateup(const float* __restrict__ gate_scale, const float* __restrict__ up_scale) {
    extern __shared__ __align__(128) char smem[];
    const uint32_t s0 = smem_u32(smem);
    const int tid = threadIdx.x;
    const int wid = tid >> 5, lane = tid & 31;
    const int rsel = lane & 15, csel = lane >> 4;
    const int wm = (wid & 1) * 64, wn = (wid >> 1) * 32;

    int mt, nt; tile_coords(blockIdx.x, NT_GU, mt, nt);
    const int m0 = mt * BM, n0 = nt * 64;
    const int off = (blockIdx.x & 1) ? (NCH_GU / 2) : 0;   // k-rotation

    const __half* pA  = g_x16  + (size_t)m0 * Hdim;
    const __half* pBg = g_gw16 + (size_t)n0 * Hdim;
    const __half* pBu = g_uw16 + (size_t)n0 * Hdim;

    const int lr = tid >> 3, lc = tid & 7;

    auto load_chunk = [&](int ch, int st) {   // ch = REAL chunk index
        uint32_t sb = s0 + st * STG_GU;
        size_t gk = (size_t)ch * BK + lc * 8;
        #pragma unroll
        for (int j = 0; j < 8; ++j)
            cpa16(sb + swzoff(lr + 16 * j, lc), pA + (size_t)(lr + 16 * j) * Hdim + gk);
        #pragma unroll
        for (int j = 0; j < 4; ++j) {
            cpa16(sb + 16384 + swzoff(lr + 16 * j, lc), pBg + (size_t)(lr + 16 * j) * Hdim + gk);
            cpa16(sb + 24576 + swzoff(lr + 16 * j, lc), pBu + (size_t)(lr + 16 * j) * Hdim + gk);
        }
        CP_COMMIT();
    };

    float cg[4][4][4], cu[4][4][4];
    #pragma unroll
    for (int g = 0; g < 4; ++g)
        #pragma unroll
        for (int n = 0; n < 4; ++n)
            #pragma unroll
            for (int j = 0; j < 4; ++j) { cg[g][n][j] = 0.f; cu[g][n][j] = 0.f; }

    {
        int c0 = off, c1 = off + 1; if (c1 >= NCH_GU) c1 -= NCH_GU;
        load_chunk(c0, 0);
        load_chunk(c1, 1);
    }

    uint32_t ah[2][4][4], bg[2][2][4], bu[2][2][4];   // buffer 1 partially live across

    for (int cc = 0; cc < NCH_GU; ++cc) {
        CP_WAIT(1);
        __syncthreads();
        const int ncc = cc + 2;
        const bool pf = ncc < NCH_GU;
        int nch = ncc + off; if (nch >= NCH_GU) nch -= NCH_GU;
        const uint32_t sb = s0 + (cc % NST) * STG_GU;
        const uint32_t nb = s0 + (ncc % NST) * STG_GU;
        const size_t gk = (size_t)nch * BK + lc * 8;

        // step-0 fragments into buffer 0
        {
            const int cvsel = csel;
            #pragma unroll
            for (int g = 0; g < 4; ++g)
                LDSM4(ah[0][g], swz(sb, wm + g * 16 + rsel, cvsel));
            #pragma unroll
            for (int bt = 0; bt < 2; ++bt) {
                LDSM4(bg[0][bt], swz(sb + 16384, wn + bt * 16 + rsel, cvsel));
                LDSM4(bu[0][bt], swz(sb + 24576, wn + bt * 16 + rsel, cvsel));
            }
        }
        // deferred MMAs: previous chunk's step-3, n=0..1 (ah[1], bg[1][0], bu[1][0])
        if (cc) {
            #pragma unroll
            for (int g = 0; g < 4; ++g)
                #pragma unroll
                for (int n = 0; n < 2; ++n) {
                    MMAF16(cg[g][n], ah[1][g], bg[1][0][n], bg[1][0][2 + n]);
                    MMAF16(cu[g][n], ah[1][g], bu[1][0][n], bu[1][0][2 + n]);
                }
        }
        #pragma unroll
        for (int s = 0; s < 4; ++s) {
            const int cur = s & 1;
            if (s < 3) {                       // load next step's frags
                const int cvsel = 2 * (s + 1) + csel;
                #pragma unroll
                for (int g = 0; g < 4; ++g)
                    LDSM4(ah[cur ^ 1][g], swz(sb, wm + g * 16 + rsel, cvsel));
                #pragma unroll
                for (int bt = 0; bt < 2; ++bt) {
                    LDSM4(bg[cur ^ 1][bt], swz(sb + 16384, wn + bt * 16 + rsel, cvsel));
                    LDSM4(bu[cur ^ 1][bt], swz(sb + 24576, wn + bt * 16 + rsel, cvsel));
                }
            }
            if (pf) {                          // quarter of next-chunk prefetch
                cpa16(nb + swzoff(lr + 16 * (2 * s), lc),
                      pA + (size_t)(lr + 16 * (2 * s)) * Hdim + gk);
                cpa16(nb + swzoff(lr + 16 * (2 * s + 1), lc),
                      pA + (size_t)(lr + 16 * (2 * s + 1)) * Hdim + gk);
                cpa16(nb + 16384 + swzoff(lr + 16 * s, lc),
                      pBg + (size_t)(lr + 16 * s) * Hdim + gk);
                cpa16(nb + 24576 + swzoff(lr + 16 * s, lc),
                      pBu + (size_t)(lr + 16 * s) * Hdim + gk);
            }
            if (s < 3) {                       // full MMA set for steps 0..2
                #pragma unroll
                for (int g = 0; g < 4; ++g)
                    #pragma unroll
                    for (int n = 0; n < 4; ++n) {
                        int bt = n >> 1, sub = n & 1;
                        MMAF16(cg[g][n], ah[cur][g], bg[cur][bt][sub], bg[cur][bt][2 + sub]);
                        MMAF16(cu[g][n], ah[cur][g], bu[cur][bt][sub], bu[cur][bt][2 + sub]);
                    }
            } else {                           // step 3: issue n=2..3 now; n=0..1 deferred
                #pragma unroll
                for (int g = 0; g < 4; ++g)
                    #pragma unroll
                    for (int n = 2; n < 4; ++n) {
                        int sub = n & 1;
                        MMAF16(cg[g][n], ah[1][g], bg[1][1][sub], bg[1][1][2 + sub]);
                        MMAF16(cu[g][n], ah[1][g], bu[1][1][sub], bu[1][1][2 + sub]);
                    }
            }
        }
        if (pf) CP_COMMIT();
    }
    // drain final chunk's deferred n=0..1
    #pragma unroll
    for (int g = 0; g < 4; ++g)
        #pragma unroll
        for (int n = 0; n < 2; ++n) {
            MMAF16(cg[g][n], ah[1][g], bg[1][0][n], bg[1][0][2 + n]);
            MMAF16(cu[g][n], ah[1][g], bu[1][0][n], bu[1][0][2 + n]);
        }

    // Epilogue: p = (g*gs)*(u*us) -> half2
    #pragma unroll
    for (int n = 0; n < 4; ++n) {
        const int cn = n0 + wn + n * 8 + (lane & 3) * 2;
        const float gs0 = gate_scale[cn], gs1 = gate_scale[cn + 1];
        const float us0 = up_scale[cn],   us1 = up_scale[cn + 1];
        #pragma unroll
        for (int g = 0; g < 4; ++g) {
            const int rr = m0 + wm + g * 16 + (lane >> 2);
            float p00 = (cg[g][n][0] * gs0) * (cu[g][n][0] * us0);
            float p01 = (cg[g][n][1] * gs1) * (cu[g][n][1] * us1);
            float p10 = (cg[g][n][2] * gs0) * (cu[g][n][2] * us0);
            float p11 = (cg[g][n][3] * gs1) * (cu[g][n][3] * us1);
            __half2 q0 = __floats2half2_rn(p00, p01);
            __half2 q1 = __floats2half2_rn(p10, p11);
            *reinterpret_cast<__half2*>(&g_p16[(size_t)rr * Idim + cn]) = q0;
            *reinterpret_cast<__half2*>(&g_p16[(size_t)(rr + 8) * Idim + cn]) = q1;
        }
    }
}

// ============================================================================
// Kernel B: down GEMM.  out = down_scale * (p @ dw^T)
// CTA: 128 threads, 2/SM. 4 warps 2m x 2n; warp 64(M) x 64(N).
// Frag double-buffer + partial step-3 deferral + parity k-rotation.
// ============================================================================
__global__ __launch_bounds__(128, 2)
void gemm_down(const float* __restrict__ down_scale, float* __restrict__ out) {
    extern __shared__ __align__(128) char smem[];
    const uint32_t s0 = smem_u32(smem);
    const int tid = threadIdx.x;
    const int wid = tid >> 5, lane = tid & 31;
    const int rsel = lane & 15, csel = lane >> 4;
    const int wm = (wid & 1) * 64, wn = (wid >> 1) * 64;

    int mt, nt; tile_coords(blockIdx.x, NT_DN, mt, nt);
    const int m0 = mt * BM, n0 = nt * 128;
    const int off = (blockIdx.x & 1) ? (NCH_DN / 2) : 0;   // k-rotation

    const __half* pA = g_p16  + (size_t)m0 * Idim;
    const __half* pB = g_dw16 + (size_t)n0 * Idim;

    const int lr = tid >> 3, lc = tid & 7;

    auto load_chunk = [&](int ch, int st) {   // ch = REAL chunk index
        uint32_t sb = s0 + st * STG_DN;
        size_t gk = (size_t)ch * BK + lc * 8;
        #pragma unroll
        for (int j = 0; j < 8; ++j) {
            cpa16(sb + swzoff(lr + 16 * j, lc),         pA + (size_t)(lr + 16 * j) * Idim + gk);
            cpa16(sb + 16384 + swzoff(lr + 16 * j, lc), pB + (size_t)(lr + 16 * j) * Idim + gk);
        }
        CP_COMMIT();
    };

    float cd[4][8][4];
    #pragma unroll
    for (int g = 0; g < 4; ++g)
        #pragma unroll
        for (int n = 0; n < 8; ++n)
            #pragma unroll
            for (int j = 0; j < 4; ++j) cd[g][n][j] = 0.f;

    {
        int c0 = off, c1 = off + 1; if (c1 >= NCH_DN) c1 -= NCH_DN;
        load_chunk(c0, 0);
        load_chunk(c1, 1);
    }

    uint32_t ah[2][4][4], bb[2][4][4];        // buffer 1 partially live across

    for (int cc = 0; cc < NCH_DN; ++cc) {
        CP_WAIT(1);
        __syncthreads();
        const int ncc = cc + 2;
        const bool pf = ncc < NCH_DN;
        int nch = ncc + off; if (nch >= NCH_DN) nch -= NCH_DN;
        const uint32_t sb = s0 + (cc % NST) * STG_DN;
        const uint32_t nb = s0 + (ncc % NST) * STG_DN;
        const size_t gk = (size_t)nch * BK + lc * 8;

        // step-0 fragments into buffer 0
        {
            const int cvsel = csel;
            #pragma unroll
            for (int g = 0; g < 4; ++g)
                LDSM4(ah[0][g], swz(sb, wm + g * 16 + rsel, cvsel));
            #pragma unroll
            for (int bt = 0; bt < 4; ++bt)
                LDSM4(bb[0][bt], swz(sb + 16384, wn + bt * 16 + rsel, cvsel));
        }
        // deferred MMAs: previous chunk's step-3, n=0..3 (ah[1], bb[1][0..1])
        if (cc) {
            #pragma unroll
            for (int g = 0; g < 4; ++g)
                #pragma unroll
                for (int n = 0; n < 4; ++n) {
                    int bt = n >> 1, sub = n & 1;
                    MMAF16(cd[g][n], ah[1][g], bb[1][bt][sub], bb[1][bt][2 + sub]);
                }
        }
        #pragma unroll
        for (int s = 0; s < 4; ++s) {
            const int cur = s & 1;
            if (s < 3) {
                const int cvsel = 2 * (s + 1) + csel;
                #pragma unroll
                for (int g = 0; g < 4; ++g)
                    LDSM4(ah[cur ^ 1][g], swz(sb, wm + g * 16 + rsel, cvsel));
                #pragma unroll
                for (int bt = 0; bt < 4; ++bt)
                    LDSM4(bb[cur ^ 1][bt], swz(sb + 16384, wn + bt * 16 + rsel, cvsel));
            }
            if (pf) {
                cpa16(nb + swzoff(lr + 16 * (2 * s), lc),
                      pA + (size_t)(lr + 16 * (2 * s)) * Idim + gk);
                cpa16(nb + swzoff(lr + 16 * (2 * s + 1), lc),
                      pA + (size_t)(lr + 16 * (2 * s + 1)) * Idim + gk);
                cpa16(nb + 16384 + swzoff(lr + 16 * (2 * s), lc),
                      pB + (size_t)(lr + 16 * (2 * s)) * Idim + gk);
                cpa16(nb + 16384 + swzoff(lr + 16 * (2 * s + 1), lc),
                      pB + (size_t)(lr + 16 * (2 * s + 1)) * Idim + gk);
            }
            if (s < 3) {                       // full MMA set for steps 0..2
                #pragma unroll
                for (int g = 0; g < 4; ++g)
                    #pragma unroll
                    for (int n = 0; n < 8; ++n) {
                        int bt = n >> 1, sub = n & 1;
                        MMAF16(cd[g][n], ah[cur][g], bb[cur][bt][sub], bb[cur][bt][2 + sub]);
                    }
            } else {                           // step 3: issue n=4..7 now; n=0..3 deferred
                #pragma unroll
                for (int g = 0; g < 4; ++g)
                    #pragma unroll
                    for (int n = 4; n < 8; ++n) {
                        int bt = n >> 1, sub = n & 1;
                        MMAF16(cd[g][n], ah[1][g], bb[1][bt][sub], bb[1][bt][2 + sub]);
                    }
            }
        }
        if (pf) CP_COMMIT();
    }
    // drain final chunk's deferred n=0..3
    #pragma unroll
    for (int g = 0; g < 4; ++g)
        #pragma unroll
        for (int n = 0; n < 4; ++n) {
            int bt = n >> 1, sub = n & 1;
            MMAF16(cd[g][n], ah[1][g], bb[1][bt][sub], bb[1][bt][2 + sub]);
        }

    #pragma unroll
    for (int n = 0; n < 8; ++n) {
        const int cn = n0 + wn + n * 8 + (lane & 3) * 2;
        const float ds0 = down_scale[cn], ds1 = down_scale[cn + 1];
        #pragma unroll
        for (int g = 0; g < 4; ++g) {
            const int rr = m0 + wm + g * 16 + (lane >> 2);
            float2 v0 = make_float2(cd[g][n][0] * ds0, cd[g][n][1] * ds1);
            float2 v1 = make_float2(cd[g][n][2] * ds0, cd[g][n][3] * ds1);
            *reinterpret_cast<float2*>(&out[(size_t)rr * Hdim + cn]) = v0;
            *reinterpret_cast<float2*>(&out[(size_t)(rr + 8) * Hdim + cn]) = v1;
        }
    }
}

// ============================================================================
// Launch
// ============================================================================
extern "C" void kernel_launch(void* const* d_in, const int* in_sizes, int n_in,
                              void* d_out, int out_size) {
    (void)in_sizes; (void)n_in; (void)out_size;
    const float* x          = (const float*)d_in[0];
    const int*   gate_wq    = (const int*)  d_in[1];
    const float* gate_scale = (const float*)d_in[2];
    const int*   up_wq      = (const int*)  d_in[3];
    const float* up_scale   = (const float*)d_in[4];
    const int*   down_wq    = (const int*)  d_in[5];
    const float* down_scale = (const float*)d_in[6];
    float* out = (float*)d_out;

    cudaFuncSetAttribute(gemm_gateup, cudaFuncAttributeMaxDynamicSharedMemorySize, SMEM_GU);
    cudaFuncSetAttribute(gemm_down,   cudaFuncAttributeMaxDynamicSharedMemorySize, SMEM_DN);

    size_t n4 = (size_t)Idim * Hdim / 4;
    pack_weights<<<(unsigned)((n4 + 255) / 256), 256>>>(gate_wq, up_wq, down_wq);
    size_t nx4 = (size_t)Mtot * Hdim / 4;
    cvt_x<<<(unsigned)((nx4 + 255) / 256), 256>>>(x);

    gemm_gateup<<<MT * NT_GU, 128, SMEM_GU>>>(gate_scale, up_scale);
    gemm_down<<<MT * NT_DN, 128, SMEM_DN>>>(down_scale, out);
}